// round 15
// baseline (speedup 1.0000x reference)
#include <cuda_runtime.h>
#include <cuda_pipeline.h>
#include <math.h>
#include <mma.h>

using namespace nvcuda;

#define B_  8
#define L_  1024
#define DM  512
#define DI  1024
#define DS  16
#define RK  32
#define NL  4

// ---------------- scratch (static device globals: allocation-guard safe) ----
__device__ float g_x  [B_*L_*DM];     // residual stream
__device__ float g_xn [B_*L_*DM];     // rmsnorm output
__device__ float g_uz [B_*L_*2*DI];   // in_proj output (u | z)
__device__ float g_u  [B_*L_*DI];     // conv+silu output
__device__ float g_dbc[B_*L_*64];     // x_proj output (dt_low | B | C)
__device__ float g_y  [B_*L_*DI];     // scan+gate output

// ---------------- small helpers ---------------------------------------------
__device__ __forceinline__ float softplus_f(float v){
    return v > 20.f ? v : log1pf(__expf(v));
}
__device__ __forceinline__ float silu_f(float v){
    return v / (1.f + __expf(-v));
}

// ---------------- canvas init: x = mask_token + pos_embed -------------------
__global__ void init_k(const float* __restrict__ mtok, const float* __restrict__ pos){
    int idx = blockIdx.x*256 + threadIdx.x;
    int c = idx % DM;
    int p = (idx / DM) % L_;
    g_x[idx] = mtok[c] + pos[p*DM + c];
}

// ---------------- scatter visible tokens (sorted ids, last-dup wins) --------
__global__ void scatter_k(const float* __restrict__ xv, const int* __restrict__ ids,
                          const float* __restrict__ pos){
    int b = blockIdx.x >> 8;
    int i = blockIdx.x & 255;
    int id = ids[b*256 + i];
    bool last = (i == 255) || (ids[b*256 + i + 1] != id);
    if (!last) return;
    for (int c = threadIdx.x; c < DM; c += blockDim.x)
        g_x[((size_t)b*L_ + id)*DM + c] = xv[((size_t)b*256 + i)*DM + c] + pos[id*DM + c];
}

// ---------------- rmsnorm: 128 threads/row, float4 ---------------------------
__global__ void rmsnorm_k(const float* __restrict__ x, const float* __restrict__ w,
                          float* __restrict__ o){
    int r = blockIdx.x;
    int t = threadIdx.x;            // 128
    float4 v = *(const float4*)&x[(size_t)r*DM + t*4];
    float s = v.x*v.x + v.y*v.y + v.z*v.z + v.w*v.w;
    #pragma unroll
    for (int off=16; off; off>>=1) s += __shfl_xor_sync(0xffffffffu, s, off);
    __shared__ float red[4];
    __shared__ float tot;
    if ((t & 31) == 0) red[t>>5] = s;
    __syncthreads();
    if (t == 0) tot = red[0] + red[1] + red[2] + red[3];
    __syncthreads();
    float rs = rsqrtf(tot * (1.f/DM) + 1e-6f);
    float4 w4 = *(const float4*)&w[t*4];
    float4 ov = make_float4(v.x*rs*w4.x, v.y*rs*w4.y, v.z*rs*w4.z, v.w*rs*w4.w);
    *(float4*)&o[(size_t)r*DM + t*4] = ov;
}

// ---------------- TF32 wmma GEMM: STG-stage cp.async, conflict-free B -------
// EPI: 0=store  1=accumulate(+=)  2=atomicAdd (split-K via blockIdx.z)
template<int BM,int BN,int BK,int WM,int WN,int EPI,int THREADS,int OCC,int STG>
__global__ void __launch_bounds__(THREADS, OCC)
tgemm_k(const float* __restrict__ A, const float* __restrict__ W,
        float* __restrict__ C, int M, int N, int K, int lda){
    constexpr int WX = BN/WN;
    constexpr int MI = WM/16;
    constexpr int NI = WN/16;
    constexpr int LDA_S = BK+4;        // banks (r*(BK+4)+c)%32 distinct for BK=16/32
    constexpr int LDB_S = BN+8;        // ldm%32==8 -> bank 8k+n, conflict-free
    constexpr int ASZ = BM*LDA_S;
    constexpr int BSZ = BK*LDB_S;

    extern __shared__ float sm[];
    float* As[STG];
    float* Bs[STG];
    #pragma unroll
    for (int i=0;i<STG;i++){
        As[i] = sm + i*(ASZ+BSZ);
        Bs[i] = sm + i*(ASZ+BSZ) + ASZ;
    }

    const int tid  = threadIdx.x;
    const int wid  = tid >> 5;
    const int wy   = wid / WX;
    const int wx   = wid % WX;
    const int rowBase = blockIdx.y*BM;
    const int colBase = blockIdx.x*BN;
    // split-K: blockIdx.z selects a K slice (gridDim.z parts)
    const int Keff = K / gridDim.z;
    const int kOff = blockIdx.z * Keff;

    wmma::fragment<wmma::accumulator,16,16,8,float> acc[MI][NI];
    #pragma unroll
    for (int i=0;i<MI;i++)
        #pragma unroll
        for (int j=0;j<NI;j++)
            wmma::fill_fragment(acc[i][j], 0.f);

    const int T = Keff/BK;

    auto prefetch = [&](int t, int buf){
        const int k0 = kOff + t*BK;
        #pragma unroll
        for (int idx=tid; idx < BM*(BK/4); idx += THREADS){
            int r  = idx / (BK/4);
            int c4 = (idx % (BK/4))*4;
            __pipeline_memcpy_async(&As[buf][r*LDA_S + c4],
                                    &A[(size_t)(rowBase+r)*lda + k0 + c4], 16);
        }
        #pragma unroll
        for (int idx=tid; idx < BK*(BN/4); idx += THREADS){
            int r  = idx / (BN/4);
            int c4 = (idx % (BN/4))*4;
            __pipeline_memcpy_async(&Bs[buf][r*LDB_S + c4],
                                    &W[(size_t)(k0+r)*N + colBase + c4], 16);
        }
        __pipeline_commit();
    };

    auto compute_tile = [&](int buf){
        #pragma unroll
        for (int kk=0; kk<BK; kk+=8){
            wmma::fragment<wmma::matrix_a,16,16,8,wmma::precision::tf32,wmma::row_major> af[MI];
            wmma::fragment<wmma::matrix_b,16,16,8,wmma::precision::tf32,wmma::row_major> bf[NI];
            #pragma unroll
            for (int i=0;i<MI;i++)
                wmma::load_matrix_sync(af[i], &As[buf][(wy*WM + i*16)*LDA_S + kk], LDA_S);
            #pragma unroll
            for (int j=0;j<NI;j++)
                wmma::load_matrix_sync(bf[j], &Bs[buf][kk*LDB_S + wx*WN + j*16], LDB_S);
            #pragma unroll
            for (int i=0;i<MI;i++)
                #pragma unroll
                for (int j=0;j<NI;j++)
                    wmma::mma_sync(acc[i][j], af[i], bf[j], acc[i][j]);
        }
    };

    if constexpr (STG == 2){
        prefetch(0, 0);
        for (int t=0; t<T; t++){
            const int buf = t & 1;
            __pipeline_wait_prior(0);
            __syncthreads();
            if (t+1 < T) prefetch(t+1, buf^1);
            compute_tile(buf);
        }
    } else {
        int P = (T < STG-1) ? T : STG-1;
        for (int i=0;i<P;i++) prefetch(i, i);
        for (int t=0; t<T; t++){
            const int buf = t % STG;
            if (t < T-1) __pipeline_wait_prior(STG-2);
            else         __pipeline_wait_prior(0);
            __syncthreads();
            if (P < T){ prefetch(P, P % STG); P++; }
            compute_tile(buf);
        }
    }

    if (EPI == 2){
        // stage whole CTA tile in smem (reuses pipeline buffers), then RED.ADD
        static_assert(EPI != 2 || BM*BN <= STG*(ASZ+BSZ), "stage fits");
        __syncthreads();
        #pragma unroll
        for (int i=0;i<MI;i++)
            #pragma unroll
            for (int j=0;j<NI;j++)
                wmma::store_matrix_sync(&sm[(wy*WM + i*16)*BN + wx*WN + j*16],
                                        acc[i][j], BN, wmma::mem_row_major);
        __syncthreads();
        for (int e=tid; e<BM*BN; e+=THREADS){
            int r = e / BN, c = e % BN;
            atomicAdd(&C[(size_t)(rowBase+r)*N + colBase + c], sm[e]);
        }
        return;
    }

    #pragma unroll
    for (int i=0;i<MI;i++){
        #pragma unroll
        for (int j=0;j<NI;j++){
            int r0 = rowBase + wy*WM + i*16;
            int c0 = colBase + wx*WN + j*16;
            float* cp = C + (size_t)r0*N + c0;
            if (EPI == 0){
                wmma::store_matrix_sync(cp, acc[i][j], N, wmma::mem_row_major);
            } else {
                wmma::fragment<wmma::accumulator,16,16,8,float> cf;
                wmma::load_matrix_sync(cf, cp, N, wmma::mem_row_major);
                #pragma unroll
                for (int e=0;e<cf.num_elements;e++) acc[i][j].x[e] += cf.x[e];
                wmma::store_matrix_sync(cp, acc[i][j], N, wmma::mem_row_major);
            }
        }
    }
}

// ---------------- causal depthwise conv(4) + bias + SiLU (float4/channel) ---
__global__ void conv_silu_k(const float* __restrict__ cw, const float* __restrict__ cb){
    int idx = blockIdx.x*256 + threadIdx.x;       // over B*L*(DI/4)
    int d4 = idx & (DI/4 - 1);
    int bt = idx >> 8;                             // b*L + t
    int t  = bt & (L_-1);
    int d  = d4 << 2;

    float4 w0 = *(const float4*)&cw[(d+0)*4];
    float4 w1 = *(const float4*)&cw[(d+1)*4];
    float4 w2 = *(const float4*)&cw[(d+2)*4];
    float4 w3 = *(const float4*)&cw[(d+3)*4];
    float4 acc = *(const float4*)&cb[d];

    #pragma unroll
    for (int k=0;k<4;k++){
        int tt = t - 3 + k;
        if (tt >= 0){
            float4 v = *(const float4*)&g_uz[(size_t)(bt - 3 + k)*(2*DI) + d];
            float a0 = (k==0)?w0.x:(k==1)?w0.y:(k==2)?w0.z:w0.w;
            float a1 = (k==0)?w1.x:(k==1)?w1.y:(k==2)?w1.z:w1.w;
            float a2 = (k==0)?w2.x:(k==1)?w2.y:(k==2)?w2.z:w2.w;
            float a3 = (k==0)?w3.x:(k==1)?w3.y:(k==2)?w3.z:w3.w;
            acc.x += v.x*a0; acc.y += v.y*a1; acc.z += v.z*a2; acc.w += v.w*a3;
        }
    }
    float4 o;
    o.x = silu_f(acc.x); o.y = silu_f(acc.y);
    o.z = silu_f(acc.z); o.w = silu_f(acc.w);
    *(float4*)&g_u[(size_t)bt*DI + d] = o;
}

// ---------------- selective scan + fused dt_proj, slim inner loop -----------
// block: 256 threads = 16 channels x 16 states. grid: B * (DI/16) = 512 blocks.
__global__ void scan_k(const float* __restrict__ A_log, const float* __restrict__ Dsk,
                       const float* __restrict__ dtw,  const float* __restrict__ dtb){
    int b    = blockIdx.x >> 6;
    int dblk = (blockIdx.x & 63) << 4;
    int ch = threadIdx.x >> 4;
    int s  = threadIdx.x & 15;
    int d  = dblk + ch;

    float a = -expf(A_log[d*DS + s]);
    float h = 0.f;

    __shared__ float swdt[32][17];                 // dt_w block [k][ch]
    __shared__ float sdsk[16];
    __shared__ float sB[64][16], sC[64][16];
    __shared__ float sdt[64][17], sdu[64][17];
    __shared__ float sg[64][16], ssk[64][16];
    __shared__ float slow[64][33];                 // dbc[:, :32] chunk

    for (int i=threadIdx.x; i<32*16; i+=256){
        int k = i >> 4, j = i & 15;
        swdt[k][j] = dtw[k*DI + dblk + j];
    }
    if (threadIdx.x < 16) sdsk[threadIdx.x] = Dsk[dblk + threadIdx.x];

    for (int t0=0; t0<L_; t0+=64){
        __syncthreads();
        for (int idx=threadIdx.x; idx<1024; idx+=256){
            int tt = idx >> 4, j = idx & 15;
            size_t row = (size_t)b*L_ + t0 + tt;
            sB [tt][j]    = g_dbc[row*64 + 32 + j];
            sC [tt][j]    = g_dbc[row*64 + 48 + j];
            float uv      = g_u [row*DI + dblk + j];
            sdu[tt][j]    = uv;                          // temp: u
            ssk[tt][j]    = uv * sdsk[j];
            sg [tt][j]    = silu_f(g_uz[row*(2*DI) + DI + dblk + j]);
            slow[tt][j]   = g_dbc[row*64 + j];
            slow[tt][j+16]= g_dbc[row*64 + 16 + j];
        }
        __syncthreads();
        // fused dt_proj + softplus; sdu := dt*u
        for (int idx=threadIdx.x; idx<1024; idx+=256){
            int tt = idx >> 4, j = idx & 15;
            float acc = dtb[dblk + j];
            #pragma unroll
            for (int k=0;k<32;k++) acc += slow[tt][k]*swdt[k][j];
            float sp = softplus_f(acc);
            sdt[tt][j] = sp;
            sdu[tt][j] *= sp;
        }
        __syncthreads();
        for (int tt=0; tt<64; tt++){
            float dA = __expf(sdt[tt][ch] * a);
            h = dA*h + sdu[tt][ch]*sB[tt][s];
            float p = h * sC[tt][s];
            p += __shfl_xor_sync(0xffffffffu, p, 8);
            p += __shfl_xor_sync(0xffffffffu, p, 4);
            p += __shfl_xor_sync(0xffffffffu, p, 2);
            p += __shfl_xor_sync(0xffffffffu, p, 1);
            if (s == 0)
                g_y[((size_t)b*L_ + t0 + tt)*DI + d] = (p + ssk[tt][ch]) * sg[tt][ch];
        }
    }
}

// ---------------- fused final rmsnorm + head --------------------------------
__global__ void rmsnorm_head_k(const float* __restrict__ x, const float* __restrict__ nw,
                               const float* __restrict__ hw, const float* __restrict__ hb,
                               float* __restrict__ out){
    int r = blockIdx.x;
    int t = threadIdx.x;
    const float* xr = x + (size_t)r*DM;
    float v0 = xr[t], v1 = xr[t+256];
    float s = v0*v0 + v1*v1;
    #pragma unroll
    for (int off=16; off; off>>=1) s += __shfl_xor_sync(0xffffffffu, s, off);
    __shared__ float red[8];
    __shared__ float tot;
    __shared__ float sxn[DM];
    if ((t & 31) == 0) red[t>>5] = s;
    __syncthreads();
    if (t == 0){
        float q = 0.f;
        #pragma unroll
        for (int i=0;i<8;i++) q += red[i];
        tot = q;
    }
    __syncthreads();
    float rs = rsqrtf(tot * (1.f/DM) + 1e-6f);
    sxn[t]     = v0 * rs * nw[t];
    sxn[t+256] = v1 * rs * nw[t+256];
    __syncthreads();

    int kg = t >> 4;
    int p  = t & 15;
    float acc = 0.f;
    #pragma unroll 8
    for (int k2=0; k2<32; k2++){
        int k = kg*32 + k2;
        acc += sxn[k] * hw[k*16 + p];
    }
    acc += __shfl_xor_sync(0xffffffffu, acc, 16);
    __shared__ float pr[8][16];
    if ((t & 31) < 16) pr[t>>5][p] = acc;
    __syncthreads();
    if (t < 16){
        float q = 0.f;
        #pragma unroll
        for (int w=0; w<8; w++) q += pr[w][t];
        out[(size_t)r*16 + t] = q + hb[t];
    }
}

// ---------------- launch ------------------------------------------------------
extern "C" void kernel_launch(void* const* d_in, const int* in_sizes, int n_in,
                              void* d_out, int out_size){
    const float* x_vis  = (const float*)d_in[0];
    const int*   ids    = (const int*)  d_in[1];
    const float* mtok   = (const float*)d_in[2];
    const float* pos    = (const float*)d_in[3];
    const float* in_w   = (const float*)d_in[4];
    const float* conv_w = (const float*)d_in[5];
    const float* conv_b = (const float*)d_in[6];
    const float* xp_w   = (const float*)d_in[7];
    const float* dt_w   = (const float*)d_in[8];
    const float* dt_b   = (const float*)d_in[9];
    const float* A_log  = (const float*)d_in[10];
    const float* Dsk    = (const float*)d_in[11];
    const float* out_w  = (const float*)d_in[12];
    const float* bn_w   = (const float*)d_in[13];
    const float* n_w    = (const float*)d_in[14];
    const float* h_w    = (const float*)d_in[15];
    const float* h_b    = (const float*)d_in[16];
    float* out = (float*)d_out;

    float *px, *pxn, *puz, *pu, *pdbc, *py;
    cudaGetSymbolAddress((void**)&px,  g_x);
    cudaGetSymbolAddress((void**)&pxn, g_xn);
    cudaGetSymbolAddress((void**)&puz, g_uz);
    cudaGetSymbolAddress((void**)&pu,  g_u);
    cudaGetSymbolAddress((void**)&pdbc,g_dbc);
    cudaGetSymbolAddress((void**)&py,  g_y);

    const int M = B_*L_;   // 8192 rows

    // smem: STG*(BM*(BK+4) + BK*(BN+8)) floats
    const int smemBig = (2*(128*20 + 16*136)) * 4;   // 37,888 B (BK=16, 2 stages)
    const int smemXp  = (3*( 32*36 + 32* 72)) * 4;   // 41,472 B (32x64, BK=32, 3 stages)

    init_k<<<(B_*L_*DM)/256, 256>>>(mtok, pos);
    scatter_k<<<B_*256, 256>>>(x_vis, ids, pos);

    for (int l=0; l<NL; l++){
        const float* inW  = in_w  + (size_t)l*DM*2*DI;
        const float* cW   = conv_w+ (size_t)l*DI*4;
        const float* cB   = conv_b+ (size_t)l*DI;
        const float* xpW  = xp_w  + (size_t)l*DI*64;
        const float* dtW  = dt_w  + (size_t)l*RK*DI;
        const float* dtB  = dt_b  + (size_t)l*DI;
        const float* aL   = A_log + (size_t)l*DI*DS;
        const float* dS   = Dsk   + (size_t)l*DI;
        const float* oW   = out_w + (size_t)l*DI*DM;
        const float* bnW  = bn_w  + (size_t)l*DM;

        rmsnorm_k<<<M, 128>>>(px, bnW, pxn);

        // uz = xn @ in_w : [8192,512] x [512,2048]  (R12-best: 64x64 wt, BK=16)
        tgemm_k<128,128,16,64,64,0,128,2,2><<<dim3(2*DI/128, M/128), 128, smemBig>>>(
            pxn, inW, puz, M, 2*DI, DM, DM);

        conv_silu_k<<<(M*DI/4)/256, 256>>>(cW, cB);

        // x_dbl = u @ xp_w : split-K=4, RED.ADD epilogue (1024 CTAs)
        cudaMemsetAsync(pdbc, 0, (size_t)M*64*sizeof(float), 0);
        tgemm_k<32,64,32,16,32,2,128,4,3><<<dim3(1, M/32, 4), 128, smemXp>>>(
            pu, xpW, pdbc, M, 64, DI, DI);

        // scan (fused dt_proj + softplus + gate, slim inner loop)
        scan_k<<<B_*(DI/16), 256>>>(aL, dS, dtW, dtB);

        // x += y @ out_w : [8192,1024] x [1024,512]  (R12-best)
        tgemm_k<128,128,16,64,64,1,128,2,2><<<dim3(DM/128, M/128), 128, smemBig>>>(
            py, oW, px, M, DM, DI, DI);
    }

    rmsnorm_head_k<<<M, 256>>>(px, n_w, h_w, h_b, out);
}

// round 16
// speedup vs baseline: 1.0948x; 1.0948x over previous
#include <cuda_runtime.h>
#include <cuda_pipeline.h>
#include <math.h>
#include <mma.h>

using namespace nvcuda;

#define B_  8
#define L_  1024
#define DM  512
#define DI  1024
#define DS  16
#define RK  32
#define NL  4

// ---------------- scratch (static device globals: allocation-guard safe) ----
__device__ float g_x  [B_*L_*DM];     // residual stream
__device__ float g_xn [B_*L_*DM];     // rmsnorm output
__device__ float g_uz [B_*L_*2*DI];   // in_proj output (u | z)
__device__ float g_u  [B_*L_*DI];     // conv+silu output
__device__ float g_dbc[B_*L_*64];     // x_proj output (dt_low | B | C)
__device__ float g_y  [B_*L_*DI];     // scan+gate output

// ---------------- small helpers ---------------------------------------------
__device__ __forceinline__ float softplus_f(float v){
    return v > 20.f ? v : log1pf(__expf(v));
}
__device__ __forceinline__ float silu_f(float v){
    return v / (1.f + __expf(-v));
}

// ---------------- canvas init: x = mask_token + pos_embed -------------------
__global__ void init_k(const float* __restrict__ mtok, const float* __restrict__ pos){
    int idx = blockIdx.x*256 + threadIdx.x;
    int c = idx % DM;
    int p = (idx / DM) % L_;
    g_x[idx] = mtok[c] + pos[p*DM + c];
}

// ---------------- scatter visible tokens (sorted ids, last-dup wins) --------
__global__ void scatter_k(const float* __restrict__ xv, const int* __restrict__ ids,
                          const float* __restrict__ pos){
    int b = blockIdx.x >> 8;
    int i = blockIdx.x & 255;
    int id = ids[b*256 + i];
    bool last = (i == 255) || (ids[b*256 + i + 1] != id);
    if (!last) return;
    for (int c = threadIdx.x; c < DM; c += blockDim.x)
        g_x[((size_t)b*L_ + id)*DM + c] = xv[((size_t)b*256 + i)*DM + c] + pos[id*DM + c];
}

// ---------------- rmsnorm: 128 threads/row, float4 ---------------------------
__global__ void rmsnorm_k(const float* __restrict__ x, const float* __restrict__ w,
                          float* __restrict__ o){
    int r = blockIdx.x;
    int t = threadIdx.x;            // 128
    float4 v = *(const float4*)&x[(size_t)r*DM + t*4];
    float s = v.x*v.x + v.y*v.y + v.z*v.z + v.w*v.w;
    #pragma unroll
    for (int off=16; off; off>>=1) s += __shfl_xor_sync(0xffffffffu, s, off);
    __shared__ float red[4];
    __shared__ float tot;
    if ((t & 31) == 0) red[t>>5] = s;
    __syncthreads();
    if (t == 0) tot = red[0] + red[1] + red[2] + red[3];
    __syncthreads();
    float rs = rsqrtf(tot * (1.f/DM) + 1e-6f);
    float4 w4 = *(const float4*)&w[t*4];
    float4 ov = make_float4(v.x*rs*w4.x, v.y*rs*w4.y, v.z*rs*w4.z, v.w*rs*w4.w);
    *(float4*)&o[(size_t)r*DM + t*4] = ov;
}

// ---------------- TF32 wmma GEMM (R12-exact): STG-stage cp.async ------------
// EPI: 0=store  1=accumulate(+=)
template<int BM,int BN,int BK,int WM,int WN,int EPI,int THREADS,int OCC,int STG>
__global__ void __launch_bounds__(THREADS, OCC)
tgemm_k(const float* __restrict__ A, const float* __restrict__ W,
        float* __restrict__ C, int M, int N, int K, int lda){
    constexpr int WX = BN/WN;
    constexpr int MI = WM/16;
    constexpr int NI = WN/16;
    constexpr int LDA_S = BK+4;        // banks (r*(BK+4)+c)%32 distinct for BK=16/32
    constexpr int LDB_S = BN+8;        // ldm%32==8 -> bank 8k+n, conflict-free
    constexpr int ASZ = BM*LDA_S;
    constexpr int BSZ = BK*LDB_S;

    extern __shared__ float sm[];
    float* As[STG];
    float* Bs[STG];
    #pragma unroll
    for (int i=0;i<STG;i++){
        As[i] = sm + i*(ASZ+BSZ);
        Bs[i] = sm + i*(ASZ+BSZ) + ASZ;
    }

    const int tid  = threadIdx.x;
    const int wid  = tid >> 5;
    const int wy   = wid / WX;
    const int wx   = wid % WX;
    const int rowBase = blockIdx.y*BM;
    const int colBase = blockIdx.x*BN;

    wmma::fragment<wmma::accumulator,16,16,8,float> acc[MI][NI];
    #pragma unroll
    for (int i=0;i<MI;i++)
        #pragma unroll
        for (int j=0;j<NI;j++)
            wmma::fill_fragment(acc[i][j], 0.f);

    const int T = K/BK;

    auto prefetch = [&](int t, int buf){
        const int k0 = t*BK;
        #pragma unroll
        for (int idx=tid; idx < BM*(BK/4); idx += THREADS){
            int r  = idx / (BK/4);
            int c4 = (idx % (BK/4))*4;
            __pipeline_memcpy_async(&As[buf][r*LDA_S + c4],
                                    &A[(size_t)(rowBase+r)*lda + k0 + c4], 16);
        }
        #pragma unroll
        for (int idx=tid; idx < BK*(BN/4); idx += THREADS){
            int r  = idx / (BN/4);
            int c4 = (idx % (BN/4))*4;
            __pipeline_memcpy_async(&Bs[buf][r*LDB_S + c4],
                                    &W[(size_t)(k0+r)*N + colBase + c4], 16);
        }
        __pipeline_commit();
    };

    auto compute_tile = [&](int buf){
        #pragma unroll
        for (int kk=0; kk<BK; kk+=8){
            wmma::fragment<wmma::matrix_a,16,16,8,wmma::precision::tf32,wmma::row_major> af[MI];
            wmma::fragment<wmma::matrix_b,16,16,8,wmma::precision::tf32,wmma::row_major> bf[NI];
            #pragma unroll
            for (int i=0;i<MI;i++)
                wmma::load_matrix_sync(af[i], &As[buf][(wy*WM + i*16)*LDA_S + kk], LDA_S);
            #pragma unroll
            for (int j=0;j<NI;j++)
                wmma::load_matrix_sync(bf[j], &Bs[buf][kk*LDB_S + wx*WN + j*16], LDB_S);
            #pragma unroll
            for (int i=0;i<MI;i++)
                #pragma unroll
                for (int j=0;j<NI;j++)
                    wmma::mma_sync(acc[i][j], af[i], bf[j], acc[i][j]);
        }
    };

    if constexpr (STG == 2){
        prefetch(0, 0);
        for (int t=0; t<T; t++){
            const int buf = t & 1;
            __pipeline_wait_prior(0);
            __syncthreads();
            if (t+1 < T) prefetch(t+1, buf^1);
            compute_tile(buf);
        }
    } else {
        int P = (T < STG-1) ? T : STG-1;
        for (int i=0;i<P;i++) prefetch(i, i);
        for (int t=0; t<T; t++){
            const int buf = t % STG;
            if (t < T-1) __pipeline_wait_prior(STG-2);
            else         __pipeline_wait_prior(0);
            __syncthreads();
            if (P < T){ prefetch(P, P % STG); P++; }
            compute_tile(buf);
        }
    }

    #pragma unroll
    for (int i=0;i<MI;i++){
        #pragma unroll
        for (int j=0;j<NI;j++){
            int r0 = rowBase + wy*WM + i*16;
            int c0 = colBase + wx*WN + j*16;
            float* cp = C + (size_t)r0*N + c0;
            if (EPI == 0){
                wmma::store_matrix_sync(cp, acc[i][j], N, wmma::mem_row_major);
            } else {
                wmma::fragment<wmma::accumulator,16,16,8,float> cf;
                wmma::load_matrix_sync(cf, cp, N, wmma::mem_row_major);
                #pragma unroll
                for (int e=0;e<cf.num_elements;e++) acc[i][j].x[e] += cf.x[e];
                wmma::store_matrix_sync(cp, acc[i][j], N, wmma::mem_row_major);
            }
        }
    }
}

// ---------------- conv+SiLU v2: 4 timesteps x 4 channels per thread ---------
// sliding window: 7 float4 loads -> 4 float4 outputs (vs 16 loads before)
__global__ void conv_silu_k(const float* __restrict__ cw, const float* __restrict__ cb){
    int idx = blockIdx.x*256 + threadIdx.x;       // over B*(L/4)*(DI/4)
    int d4 = idx & (DI/4 - 1);
    int r  = idx >> 8;                             // b*(L/4) + t4
    int t4 = r & (L_/4 - 1);
    int b  = r >> 8;                               // L_/4 = 256
    int d  = d4 << 2;
    size_t rowBase = (size_t)b*L_;

    float4 w0 = *(const float4*)&cw[(d+0)*4];
    float4 w1 = *(const float4*)&cw[(d+1)*4];
    float4 w2 = *(const float4*)&cw[(d+2)*4];
    float4 w3 = *(const float4*)&cw[(d+3)*4];
    float4 bias = *(const float4*)&cb[d];

    float4 v[7];
    #pragma unroll
    for (int j=0;j<7;j++){
        int tl = t4*4 - 3 + j;
        if (tl >= 0)
            v[j] = *(const float4*)&g_uz[(rowBase + tl)*(2*DI) + d];
        else
            v[j] = make_float4(0.f,0.f,0.f,0.f);
    }

    #pragma unroll
    for (int i=0;i<4;i++){
        float4 a = bias;
        #pragma unroll
        for (int k=0;k<4;k++){
            float4 vv = v[i+k];
            float c0 = (k==0)?w0.x:(k==1)?w0.y:(k==2)?w0.z:w0.w;
            float c1 = (k==0)?w1.x:(k==1)?w1.y:(k==2)?w1.z:w1.w;
            float c2 = (k==0)?w2.x:(k==1)?w2.y:(k==2)?w2.z:w2.w;
            float c3 = (k==0)?w3.x:(k==1)?w3.y:(k==2)?w3.z:w3.w;
            a.x += vv.x*c0; a.y += vv.y*c1; a.z += vv.z*c2; a.w += vv.w*c3;
        }
        float4 o;
        o.x = silu_f(a.x); o.y = silu_f(a.y);
        o.z = silu_f(a.z); o.w = silu_f(a.w);
        *(float4*)&g_u[(rowBase + t4*4 + i)*DI + d] = o;
    }
}

// ---------------- selective scan + fused dt_proj, slim inner loop -----------
// block: 256 threads = 16 channels x 16 states. grid: B * (DI/16) = 512 blocks.
__global__ void scan_k(const float* __restrict__ A_log, const float* __restrict__ Dsk,
                       const float* __restrict__ dtw,  const float* __restrict__ dtb){
    int b    = blockIdx.x >> 6;
    int dblk = (blockIdx.x & 63) << 4;
    int ch = threadIdx.x >> 4;
    int s  = threadIdx.x & 15;
    int d  = dblk + ch;

    float a = -expf(A_log[d*DS + s]);
    float h = 0.f;

    __shared__ float swdt[32][17];                 // dt_w block [k][ch]
    __shared__ float sdsk[16];
    __shared__ float sB[64][16], sC[64][16];
    __shared__ float sdt[64][17], sdu[64][17];
    __shared__ float sg[64][16], ssk[64][16];
    __shared__ float slow[64][33];                 // dbc[:, :32] chunk

    for (int i=threadIdx.x; i<32*16; i+=256){
        int k = i >> 4, j = i & 15;
        swdt[k][j] = dtw[k*DI + dblk + j];
    }
    if (threadIdx.x < 16) sdsk[threadIdx.x] = Dsk[dblk + threadIdx.x];

    for (int t0=0; t0<L_; t0+=64){
        __syncthreads();
        for (int idx=threadIdx.x; idx<1024; idx+=256){
            int tt = idx >> 4, j = idx & 15;
            size_t row = (size_t)b*L_ + t0 + tt;
            sB [tt][j]    = g_dbc[row*64 + 32 + j];
            sC [tt][j]    = g_dbc[row*64 + 48 + j];
            float uv      = g_u [row*DI + dblk + j];
            sdu[tt][j]    = uv;                          // temp: u
            ssk[tt][j]    = uv * sdsk[j];
            sg [tt][j]    = silu_f(g_uz[row*(2*DI) + DI + dblk + j]);
            slow[tt][j]   = g_dbc[row*64 + j];
            slow[tt][j+16]= g_dbc[row*64 + 16 + j];
        }
        __syncthreads();
        // fused dt_proj + softplus; sdu := dt*u
        for (int idx=threadIdx.x; idx<1024; idx+=256){
            int tt = idx >> 4, j = idx & 15;
            float acc = dtb[dblk + j];
            #pragma unroll
            for (int k=0;k<32;k++) acc += slow[tt][k]*swdt[k][j];
            float sp = softplus_f(acc);
            sdt[tt][j] = sp;
            sdu[tt][j] *= sp;
        }
        __syncthreads();
        for (int tt=0; tt<64; tt++){
            float dA = __expf(sdt[tt][ch] * a);
            h = dA*h + sdu[tt][ch]*sB[tt][s];
            float p = h * sC[tt][s];
            p += __shfl_xor_sync(0xffffffffu, p, 8);
            p += __shfl_xor_sync(0xffffffffu, p, 4);
            p += __shfl_xor_sync(0xffffffffu, p, 2);
            p += __shfl_xor_sync(0xffffffffu, p, 1);
            if (s == 0)
                g_y[((size_t)b*L_ + t0 + tt)*DI + d] = (p + ssk[tt][ch]) * sg[tt][ch];
        }
    }
}

// ---------------- fused final rmsnorm + head --------------------------------
__global__ void rmsnorm_head_k(const float* __restrict__ x, const float* __restrict__ nw,
                               const float* __restrict__ hw, const float* __restrict__ hb,
                               float* __restrict__ out){
    int r = blockIdx.x;
    int t = threadIdx.x;
    const float* xr = x + (size_t)r*DM;
    float v0 = xr[t], v1 = xr[t+256];
    float s = v0*v0 + v1*v1;
    #pragma unroll
    for (int off=16; off; off>>=1) s += __shfl_xor_sync(0xffffffffu, s, off);
    __shared__ float red[8];
    __shared__ float tot;
    __shared__ float sxn[DM];
    if ((t & 31) == 0) red[t>>5] = s;
    __syncthreads();
    if (t == 0){
        float q = 0.f;
        #pragma unroll
        for (int i=0;i<8;i++) q += red[i];
        tot = q;
    }
    __syncthreads();
    float rs = rsqrtf(tot * (1.f/DM) + 1e-6f);
    sxn[t]     = v0 * rs * nw[t];
    sxn[t+256] = v1 * rs * nw[t+256];
    __syncthreads();

    int kg = t >> 4;
    int p  = t & 15;
    float acc = 0.f;
    #pragma unroll 8
    for (int k2=0; k2<32; k2++){
        int k = kg*32 + k2;
        acc += sxn[k] * hw[k*16 + p];
    }
    acc += __shfl_xor_sync(0xffffffffu, acc, 16);
    __shared__ float pr[8][16];
    if ((t & 31) < 16) pr[t>>5][p] = acc;
    __syncthreads();
    if (t < 16){
        float q = 0.f;
        #pragma unroll
        for (int w=0; w<8; w++) q += pr[w][t];
        out[(size_t)r*16 + t] = q + hb[t];
    }
}

// ---------------- launch ------------------------------------------------------
extern "C" void kernel_launch(void* const* d_in, const int* in_sizes, int n_in,
                              void* d_out, int out_size){
    const float* x_vis  = (const float*)d_in[0];
    const int*   ids    = (const int*)  d_in[1];
    const float* mtok   = (const float*)d_in[2];
    const float* pos    = (const float*)d_in[3];
    const float* in_w   = (const float*)d_in[4];
    const float* conv_w = (const float*)d_in[5];
    const float* conv_b = (const float*)d_in[6];
    const float* xp_w   = (const float*)d_in[7];
    const float* dt_w   = (const float*)d_in[8];
    const float* dt_b   = (const float*)d_in[9];
    const float* A_log  = (const float*)d_in[10];
    const float* Dsk    = (const float*)d_in[11];
    const float* out_w  = (const float*)d_in[12];
    const float* bn_w   = (const float*)d_in[13];
    const float* n_w    = (const float*)d_in[14];
    const float* h_w    = (const float*)d_in[15];
    const float* h_b    = (const float*)d_in[16];
    float* out = (float*)d_out;

    float *px, *pxn, *puz, *pu, *pdbc, *py;
    cudaGetSymbolAddress((void**)&px,  g_x);
    cudaGetSymbolAddress((void**)&pxn, g_xn);
    cudaGetSymbolAddress((void**)&puz, g_uz);
    cudaGetSymbolAddress((void**)&pu,  g_u);
    cudaGetSymbolAddress((void**)&pdbc,g_dbc);
    cudaGetSymbolAddress((void**)&py,  g_y);

    const int M = B_*L_;   // 8192 rows

    // smem: STG*(BM*(BK+4) + BK*(BN+8)) floats
    const int smemBig = (2*(128*20 + 16*136)) * 4;   // 37,888 B (BK=16, 2 stages)
    const int smemXp  = (3*( 32*36 + 32* 72)) * 4;   // 41,472 B (32x64, BK=32, 3 stages)

    init_k<<<(B_*L_*DM)/256, 256>>>(mtok, pos);
    scatter_k<<<B_*256, 256>>>(x_vis, ids, pos);

    for (int l=0; l<NL; l++){
        const float* inW  = in_w  + (size_t)l*DM*2*DI;
        const float* cW   = conv_w+ (size_t)l*DI*4;
        const float* cB   = conv_b+ (size_t)l*DI;
        const float* xpW  = xp_w  + (size_t)l*DI*64;
        const float* dtW  = dt_w  + (size_t)l*RK*DI;
        const float* dtB  = dt_b  + (size_t)l*DI;
        const float* aL   = A_log + (size_t)l*DI*DS;
        const float* dS   = Dsk   + (size_t)l*DI;
        const float* oW   = out_w + (size_t)l*DI*DM;
        const float* bnW  = bn_w  + (size_t)l*DM;

        rmsnorm_k<<<M, 128>>>(px, bnW, pxn);

        // uz = xn @ in_w : [8192,512] x [512,2048]  (R12-best: 64x64 wt, BK=16)
        tgemm_k<128,128,16,64,64,0,128,2,2><<<dim3(2*DI/128, M/128), 128, smemBig>>>(
            pxn, inW, puz, M, 2*DI, DM, DM);

        conv_silu_k<<<(B_*(L_/4)*(DI/4))/256, 256>>>(cW, cB);

        // x_dbl = u @ xp_w : [8192,1024] x [1024,64]  (3-stage pipeline, 4/SM)
        tgemm_k<32,64,32,16,32,0,128,4,3><<<dim3(1, M/32), 128, smemXp>>>(
            pu, xpW, pdbc, M, 64, DI, DI);

        // scan (fused dt_proj + softplus + gate, slim inner loop)
        scan_k<<<B_*(DI/16), 256>>>(aL, dS, dtW, dtB);

        // x += y @ out_w : [8192,1024] x [1024,512]  (R12-best)
        tgemm_k<128,128,16,64,64,1,128,2,2><<<dim3(DM/128, M/128), 128, smemBig>>>(
            py, oW, px, M, DM, DI, DI);
    }

    rmsnorm_head_k<<<M, 256>>>(px, n_w, h_w, h_b, out);
}